// round 1
// baseline (speedup 1.0000x reference)
#include <cuda_runtime.h>
#include <math.h>

#define B_SZ   4
#define T_SEQ  2048
#define C_DIM  1024
#define C3     3072
#define NH     16
#define HD     64
#define PAD    68   // smem row pitch (floats): multiple of 4 (float4) + bank skew

// Scratch (allocation-free rule: __device__ globals)
__device__ float g_qkv[(size_t)B_SZ * T_SEQ * C3];    // [B,T,3C]
__device__ float g_att[(size_t)B_SZ * T_SEQ * C_DIM]; // [B,T,C] (heads merged back)

// ---------------------------------------------------------------------------
// SGEMM "NT": C[m,n] = sum_k A[m,k] * B[n,k]
// A row-major [M,K], B row-major [N,K], C row-major [M,N].
// 128x128 tile, BK=8, 256 threads, 8x8 per-thread register tile.
// Requires M%128==0, N%128==0, K%8==0 (true for all three calls).
// ---------------------------------------------------------------------------
__global__ __launch_bounds__(256) void sgemm_nt(const float* __restrict__ A,
                                                const float* __restrict__ B,
                                                float* __restrict__ C,
                                                int M, int N, int K) {
    __shared__ float As[8][128];
    __shared__ float Bs[8][128];

    const int tid = threadIdx.x;
    const int bm = blockIdx.y * 128;
    const int bn = blockIdx.x * 128;
    const int tx = tid & 15;   // column group (8 cols each)
    const int ty = tid >> 4;   // row group (8 rows each)

    // Load mapping: 128 rows x 8 k -> each thread one float4
    const int lr = tid >> 1;          // 0..127 tile row
    const int lk = (tid & 1) << 2;    // 0 or 4

    const float* Ap = A + (size_t)(bm + lr) * K + lk;
    const float* Bp = B + (size_t)(bn + lr) * K + lk;

    float acc[8][8];
#pragma unroll
    for (int r = 0; r < 8; r++)
#pragma unroll
        for (int c = 0; c < 8; c++) acc[r][c] = 0.0f;

    for (int k0 = 0; k0 < K; k0 += 8) {
        float4 a = *(const float4*)(Ap + k0);
        float4 b = *(const float4*)(Bp + k0);
        __syncthreads();
        As[lk + 0][lr] = a.x; As[lk + 1][lr] = a.y;
        As[lk + 2][lr] = a.z; As[lk + 3][lr] = a.w;
        Bs[lk + 0][lr] = b.x; Bs[lk + 1][lr] = b.y;
        Bs[lk + 2][lr] = b.z; Bs[lk + 3][lr] = b.w;
        __syncthreads();
#pragma unroll
        for (int k = 0; k < 8; k++) {
            float ar[8], br[8];
            *(float4*)&ar[0] = *(const float4*)&As[k][ty * 8];
            *(float4*)&ar[4] = *(const float4*)&As[k][ty * 8 + 4];
            *(float4*)&br[0] = *(const float4*)&Bs[k][tx * 8];
            *(float4*)&br[4] = *(const float4*)&Bs[k][tx * 8 + 4];
#pragma unroll
            for (int r = 0; r < 8; r++)
#pragma unroll
                for (int c = 0; c < 8; c++) acc[r][c] += ar[r] * br[c];
        }
    }

#pragma unroll
    for (int r = 0; r < 8; r++) {
        float* Cp = C + (size_t)(bm + ty * 8 + r) * N + bn + tx * 8;
        float4 o0 = make_float4(acc[r][0], acc[r][1], acc[r][2], acc[r][3]);
        float4 o1 = make_float4(acc[r][4], acc[r][5], acc[r][6], acc[r][7]);
        *(float4*)(Cp)     = o0;
        *(float4*)(Cp + 4) = o1;
    }
}

// ---------------------------------------------------------------------------
// Flash attention (causal), fp32. One CTA per (b, h, 64-query tile).
// 256 threads as 16x16; each thread owns a 4x4 subtile.
// Q,K stored d-major in smem (GEMM-style S=Q*K^T); V row-major; P staged
// through smem for the P*V product. Online softmax with shfl row reductions.
// ---------------------------------------------------------------------------
__global__ __launch_bounds__(256) void flash_attn(const float* __restrict__ qkv,
                                                  float* __restrict__ out) {
    extern __shared__ float sm[];
    float* Qs = sm;                 // [HD][PAD], d-major: Qs[d*PAD + i]
    float* Ks = Qs + HD * PAD;      // [HD][PAD], d-major: Ks[d*PAD + j]
    float* Vs = Ks + HD * PAD;      // [64][PAD], row-major: Vs[j*PAD + d]
    float* Ps = Vs + 64 * PAD;      // [64][PAD], row-major: Ps[i*PAD + j]

    const int tid = threadIdx.x;
    const int tx = tid & 15;        // score-column group / out-dim group
    const int ty = tid >> 4;        // query-row group
    const int qt = blockIdx.x;
    const int h  = blockIdx.y;
    const int b  = blockIdx.z;
    const int q0 = qt * 64;

    const float* qb = qkv + (size_t)b * T_SEQ * C3 + (size_t)h * HD;
    const float* kb = qb + C_DIM;
    const float* vb = qb + 2 * C_DIM;

    // Load Q tile (64 rows x 64 dims), transposed into d-major smem
#pragma unroll
    for (int r = 0; r < 4; r++) {
        int idx = tid + r * 256;
        int i = idx >> 4;
        int d0 = (idx & 15) << 2;
        float4 q4 = *(const float4*)(qb + (size_t)(q0 + i) * C3 + d0);
        Qs[(d0 + 0) * PAD + i] = q4.x;
        Qs[(d0 + 1) * PAD + i] = q4.y;
        Qs[(d0 + 2) * PAD + i] = q4.z;
        Qs[(d0 + 3) * PAD + i] = q4.w;
    }

    float m[4], l[4], o[4][4];
#pragma unroll
    for (int r = 0; r < 4; r++) {
        m[r] = -1e30f;
        l[r] = 0.0f;
#pragma unroll
        for (int c = 0; c < 4; c++) o[r][c] = 0.0f;
    }

    const float scale = 0.125f; // 1/sqrt(64)

    for (int kt = 0; kt <= qt; kt++) {
        const int k0 = kt * 64;
        __syncthreads();  // previous tile's Ks/Vs/Ps consumers done
        // Load K (transposed) and V (row-major) tiles
#pragma unroll
        for (int r = 0; r < 4; r++) {
            int idx = tid + r * 256;
            int j = idx >> 4;
            int d0 = (idx & 15) << 2;
            float4 k4 = *(const float4*)(kb + (size_t)(k0 + j) * C3 + d0);
            Ks[(d0 + 0) * PAD + j] = k4.x;
            Ks[(d0 + 1) * PAD + j] = k4.y;
            Ks[(d0 + 2) * PAD + j] = k4.z;
            Ks[(d0 + 3) * PAD + j] = k4.w;
            float4 v4 = *(const float4*)(vb + (size_t)(k0 + j) * C3 + d0);
            *(float4*)&Vs[j * PAD + d0] = v4;
        }
        __syncthreads();

        // S = Q * K^T (4x4 per thread)
        float s[4][4];
#pragma unroll
        for (int r = 0; r < 4; r++)
#pragma unroll
            for (int c = 0; c < 4; c++) s[r][c] = 0.0f;

#pragma unroll 8
        for (int d = 0; d < HD; d++) {
            float4 qv = *(const float4*)&Qs[d * PAD + ty * 4];
            float4 kv = *(const float4*)&Ks[d * PAD + tx * 4];
            float qr[4] = {qv.x, qv.y, qv.z, qv.w};
            float kr[4] = {kv.x, kv.y, kv.z, kv.w};
#pragma unroll
            for (int r = 0; r < 4; r++)
#pragma unroll
                for (int c = 0; c < 4; c++) s[r][c] += qr[r] * kr[c];
        }

        // Scale + causal mask (only the diagonal tile needs masking)
#pragma unroll
        for (int r = 0; r < 4; r++)
#pragma unroll
            for (int c = 0; c < 4; c++) s[r][c] *= scale;
        if (kt == qt) {
#pragma unroll
            for (int r = 0; r < 4; r++) {
                int ig = ty * 4 + r;
#pragma unroll
                for (int c = 0; c < 4; c++) {
                    int jg = tx * 4 + c;
                    if (jg > ig) s[r][c] = -1e30f;
                }
            }
        }

        // Online softmax update per row
#pragma unroll
        for (int r = 0; r < 4; r++) {
            float rm = fmaxf(fmaxf(s[r][0], s[r][1]), fmaxf(s[r][2], s[r][3]));
            rm = fmaxf(rm, __shfl_xor_sync(0xffffffffu, rm, 1));
            rm = fmaxf(rm, __shfl_xor_sync(0xffffffffu, rm, 2));
            rm = fmaxf(rm, __shfl_xor_sync(0xffffffffu, rm, 4));
            rm = fmaxf(rm, __shfl_xor_sync(0xffffffffu, rm, 8));
            float mn = fmaxf(m[r], rm);
            float alpha = __expf(m[r] - mn);
            m[r] = mn;
            float rs = 0.0f;
#pragma unroll
            for (int c = 0; c < 4; c++) {
                s[r][c] = __expf(s[r][c] - mn);
                rs += s[r][c];
            }
            rs += __shfl_xor_sync(0xffffffffu, rs, 1);
            rs += __shfl_xor_sync(0xffffffffu, rs, 2);
            rs += __shfl_xor_sync(0xffffffffu, rs, 4);
            rs += __shfl_xor_sync(0xffffffffu, rs, 8);
            l[r] = l[r] * alpha + rs;
#pragma unroll
            for (int c = 0; c < 4; c++) o[r][c] *= alpha;
            *(float4*)&Ps[(ty * 4 + r) * PAD + tx * 4] =
                make_float4(s[r][0], s[r][1], s[r][2], s[r][3]);
        }
        __syncthreads();

        // O += P * V
#pragma unroll 4
        for (int j = 0; j < 64; j++) {
            float4 v4 = *(const float4*)&Vs[j * PAD + tx * 4];
#pragma unroll
            for (int r = 0; r < 4; r++) {
                float p = Ps[(ty * 4 + r) * PAD + j];
                o[r][0] += p * v4.x;
                o[r][1] += p * v4.y;
                o[r][2] += p * v4.z;
                o[r][3] += p * v4.w;
            }
        }
    }

    // Epilogue: normalize and write [B,T,C] with C-index = h*64 + d
#pragma unroll
    for (int r = 0; r < 4; r++) {
        float inv = 1.0f / l[r];
        float4 w = make_float4(o[r][0] * inv, o[r][1] * inv,
                               o[r][2] * inv, o[r][3] * inv);
        *(float4*)&out[((size_t)b * T_SEQ + q0 + ty * 4 + r) * C_DIM
                       + h * HD + tx * 4] = w;
    }
}

// ---------------------------------------------------------------------------
extern "C" void kernel_launch(void* const* d_in, const int* in_sizes, int n_in,
                              void* d_out, int out_size) {
    const float* x      = (const float*)d_in[0];
    const float* w_qkv  = (const float*)d_in[1];
    const float* w_proj = (const float*)d_in[2];
    float* out = (float*)d_out;

    float *qkv, *att;
    cudaGetSymbolAddress((void**)&qkv, g_qkv);
    cudaGetSymbolAddress((void**)&att, g_att);

    const int M = B_SZ * T_SEQ;  // 8192

    // 1) qkv = x @ w_qkv^T   [8192,1024]x[3072,1024]^T -> [8192,3072]
    {
        dim3 grid(C3 / 128, M / 128);
        sgemm_nt<<<grid, 256>>>(x, w_qkv, qkv, M, C3, C_DIM);
    }

    // 2) fused causal flash attention -> att [B,T,C]
    {
        const int smem_bytes = 4 * HD * PAD * (int)sizeof(float); // 69632
        cudaFuncSetAttribute(flash_attn,
                             cudaFuncAttributeMaxDynamicSharedMemorySize,
                             smem_bytes);
        dim3 grid(T_SEQ / 64, NH, B_SZ);
        flash_attn<<<grid, 256, smem_bytes>>>(qkv, att);
    }

    // 3) out = att @ w_proj^T  [8192,1024]x[1024,1024]^T -> [8192,1024]
    {
        dim3 grid(C_DIM / 128, M / 128);
        sgemm_nt<<<grid, 256>>>(att, w_proj, out, M, C_DIM, C_DIM);
    }
}

// round 3
// speedup vs baseline: 1.6645x; 1.6645x over previous
#include <cuda_runtime.h>
#include <cuda_bf16.h>
#include <cstdint>
#include <math.h>

#define B_SZ   4
#define T_SEQ  2048
#define C_DIM  1024
#define C3     3072
#define NH     16
#define HD     64
#define PAD    68
#define MTOT   (B_SZ * T_SEQ)   // 8192

// ---------------------------------------------------------------------------
// Scratch (__device__ globals; no allocation allowed)
// ---------------------------------------------------------------------------
__device__ float g_qkv[(size_t)MTOT * C3];
__device__ float g_att[(size_t)MTOT * C_DIM];
__device__ __nv_bfloat16 g_xhi[(size_t)MTOT * C_DIM];
__device__ __nv_bfloat16 g_xlo[(size_t)MTOT * C_DIM];
__device__ __nv_bfloat16 g_ahi[(size_t)MTOT * C_DIM];
__device__ __nv_bfloat16 g_alo[(size_t)MTOT * C_DIM];
__device__ __nv_bfloat16 g_wqhi[(size_t)C3 * C_DIM];
__device__ __nv_bfloat16 g_wqlo[(size_t)C3 * C_DIM];
__device__ __nv_bfloat16 g_wphi[(size_t)C_DIM * C_DIM];
__device__ __nv_bfloat16 g_wplo[(size_t)C_DIM * C_DIM];

// ---------------------------------------------------------------------------
// Baseline-PTX building blocks (sm_80+: work on plain compute_103)
// ---------------------------------------------------------------------------
__device__ __forceinline__ uint32_t smem_u32(const void* p) {
    uint32_t a;
    asm("{ .reg .u64 t; cvta.to.shared.u64 t, %1; cvt.u32.u64 %0, t; }"
        : "=r"(a) : "l"(p));
    return a;
}

#define CP_ASYNC16(saddr, gptr) \
    asm volatile("cp.async.cg.shared.global [%0], [%1], 16;" \
                 :: "r"(saddr), "l"(gptr))
#define CP_COMMIT() asm volatile("cp.async.commit_group;" ::: "memory")
#define CP_WAIT(n)  asm volatile("cp.async.wait_group %0;" :: "n"(n) : "memory")

#define LDMATRIX_X4(R, addr) \
    asm volatile("ldmatrix.sync.aligned.m8n8.x4.shared.b16 {%0,%1,%2,%3}, [%4];" \
                 : "=r"((R)[0]), "=r"((R)[1]), "=r"((R)[2]), "=r"((R)[3]) \
                 : "r"(addr))

#define MMA16816(D, A, B0, B1) \
    asm volatile("mma.sync.aligned.m16n8k16.row.col.f32.bf16.bf16.f32 " \
                 "{%0,%1,%2,%3}, {%4,%5,%6,%7}, {%8,%9}, {%0,%1,%2,%3};" \
                 : "+f"((D)[0]), "+f"((D)[1]), "+f"((D)[2]), "+f"((D)[3]) \
                 : "r"((A)[0]), "r"((A)[1]), "r"((A)[2]), "r"((A)[3]), \
                   "r"(B0), "r"(B1))

// ---------------------------------------------------------------------------
// fp32 -> (bf16 hi, bf16 lo) split
// ---------------------------------------------------------------------------
__global__ void split_bf16(const float* __restrict__ x,
                           __nv_bfloat16* __restrict__ hi,
                           __nv_bfloat16* __restrict__ lo, int n4) {
    int i = blockIdx.x * blockDim.x + threadIdx.x;
    if (i >= n4) return;
    float4 v = ((const float4*)x)[i];
    __nv_bfloat16 h0 = __float2bfloat16(v.x);
    __nv_bfloat16 h1 = __float2bfloat16(v.y);
    __nv_bfloat16 h2 = __float2bfloat16(v.z);
    __nv_bfloat16 h3 = __float2bfloat16(v.w);
    __nv_bfloat16 l0 = __float2bfloat16(v.x - __bfloat162float(h0));
    __nv_bfloat16 l1 = __float2bfloat16(v.y - __bfloat162float(h1));
    __nv_bfloat16 l2 = __float2bfloat16(v.z - __bfloat162float(h2));
    __nv_bfloat16 l3 = __float2bfloat16(v.w - __bfloat162float(h3));
    ((__nv_bfloat162*)hi)[2 * i]     = __nv_bfloat162(h0, h1);
    ((__nv_bfloat162*)hi)[2 * i + 1] = __nv_bfloat162(h2, h3);
    ((__nv_bfloat162*)lo)[2 * i]     = __nv_bfloat162(l0, l1);
    ((__nv_bfloat162*)lo)[2 * i + 1] = __nv_bfloat162(l2, l3);
}

// ---------------------------------------------------------------------------
// bf16x3 GEMM NT via mma.sync: C[m,n] = sum_k A[m,k]*B[n,k], fp32-accurate.
// CTA tile 128x128, BK=32, 8 warps (2m x 4n), warp tile 64x32.
// cp.async double-buffered smem; ldmatrix fragment loads (pad-40 rows).
// Requires M%128==0, N%128==0, K%32==0.
// ---------------------------------------------------------------------------
#define BK 32
#define SSTRIDE 40                                 // bf16 elems per smem row
#define SROWB (SSTRIDE * 2)                        // 80 bytes
#define TILE_SMB (128 * SROWB)                     // 10240
#define STAGE_SMB (4 * TILE_SMB)                   // 40960
#define GSMEM_TOTAL (2 * STAGE_SMB)                // 81920

__global__ __launch_bounds__(256)
void gemm_mma_bf16x3(const __nv_bfloat16* __restrict__ Ahi,
                     const __nv_bfloat16* __restrict__ Alo,
                     const __nv_bfloat16* __restrict__ Bhi,
                     const __nv_bfloat16* __restrict__ Blo,
                     float* __restrict__ C, int M, int N, int K) {
    extern __shared__ char smem[];
    const uint32_t sb = smem_u32(smem);
    const int tid  = threadIdx.x;
    const int wid  = tid >> 5;
    const int lane = tid & 31;
    const int bm = blockIdx.y * 128;
    const int bn = blockIdx.x * 128;
    const int wm = (wid >> 2) * 64;   // warp row base within tile
    const int wn = (wid & 3) * 32;    // warp col base within tile

    float acc[4][4][4];
#pragma unroll
    for (int mt = 0; mt < 4; mt++)
#pragma unroll
        for (int nt = 0; nt < 4; nt++)
#pragma unroll
            for (int r = 0; r < 4; r++) acc[mt][nt][r] = 0.0f;

    // stage loader: 4 tiles x 128 rows x 32 bf16, 16B per cp.async
    auto load_stage = [&](int chunk, int buf) {
        const uint32_t stage = sb + buf * STAGE_SMB;
        const size_t k0 = (size_t)chunk * BK;
#pragma unroll
        for (int i = 0; i < 2; i++) {
            const int id  = tid + i * 256;     // 0..511
            const int row = id >> 2;           // 0..127
            const int c8  = id & 3;            // 0..3
            const uint32_t soff = (uint32_t)(row * SROWB + c8 * 16);
            const size_t aoff = (size_t)(bm + row) * K + k0 + c8 * 8;
            const size_t boff = (size_t)(bn + row) * K + k0 + c8 * 8;
            CP_ASYNC16(stage + soff,                Ahi + aoff);
            CP_ASYNC16(stage + TILE_SMB + soff,     Alo + aoff);
            CP_ASYNC16(stage + 2 * TILE_SMB + soff, Bhi + boff);
            CP_ASYNC16(stage + 3 * TILE_SMB + soff, Blo + boff);
        }
    };

    const int nch = K / BK;
    load_stage(0, 0);
    CP_COMMIT();

    // ldmatrix lane addressing (constant per thread)
    const uint32_t a_row = (uint32_t)(lane & 15);
    const uint32_t a_col = (uint32_t)((lane >> 4) << 3);
    const uint32_t b_row = (uint32_t)(((lane >> 4) << 3) + (lane & 7));
    const uint32_t b_col = (uint32_t)(((lane >> 3) & 1) << 3);

    for (int c = 0; c < nch; c++) {
        const int buf = c & 1;
        if (c + 1 < nch) {
            load_stage(c + 1, buf ^ 1);
            CP_COMMIT();
            CP_WAIT(1);
        } else {
            CP_WAIT(0);
        }
        __syncthreads();

        const uint32_t sAh = sb + buf * STAGE_SMB;
        const uint32_t sAl = sAh + TILE_SMB;
        const uint32_t sBh = sAh + 2 * TILE_SMB;
        const uint32_t sBl = sAh + 3 * TILE_SMB;

#pragma unroll
        for (int ks = 0; ks < 2; ks++) {
            const uint32_t k0 = ks * 16;
            uint32_t ah[4][4], al[4][4], bh[2][4], bl[2][4];
#pragma unroll
            for (int mt = 0; mt < 4; mt++) {
                const uint32_t off = (uint32_t)(wm + mt * 16 + a_row) * SROWB
                                   + (k0 + a_col) * 2;
                LDMATRIX_X4(ah[mt], sAh + off);
                LDMATRIX_X4(al[mt], sAl + off);
            }
#pragma unroll
            for (int ng = 0; ng < 2; ng++) {
                const uint32_t off = (uint32_t)(wn + ng * 16 + b_row) * SROWB
                                   + (k0 + b_col) * 2;
                LDMATRIX_X4(bh[ng], sBh + off);
                LDMATRIX_X4(bl[ng], sBl + off);
            }
#pragma unroll
            for (int mt = 0; mt < 4; mt++) {
#pragma unroll
                for (int nt = 0; nt < 4; nt++) {
                    const int ng = nt >> 1;
                    const int rb = (nt & 1) * 2;
                    MMA16816(acc[mt][nt], ah[mt], bh[ng][rb], bh[ng][rb + 1]);
                    MMA16816(acc[mt][nt], ah[mt], bl[ng][rb], bl[ng][rb + 1]);
                    MMA16816(acc[mt][nt], al[mt], bh[ng][rb], bh[ng][rb + 1]);
                }
            }
        }
        __syncthreads();
    }

    // Epilogue: c0,c1 at (row, col..col+1), c2,c3 at (row+8, ...)
    const int erow = bm + wm + (lane >> 2);
    const int ecol = bn + wn + (lane & 3) * 2;
#pragma unroll
    for (int mt = 0; mt < 4; mt++) {
#pragma unroll
        for (int nt = 0; nt < 4; nt++) {
            float* p = C + (size_t)(erow + mt * 16) * N + ecol + nt * 8;
            *(float2*)p           = make_float2(acc[mt][nt][0], acc[mt][nt][1]);
            *(float2*)(p + 8 * N) = make_float2(acc[mt][nt][2], acc[mt][nt][3]);
        }
    }
}

// ---------------------------------------------------------------------------
// Flash attention (causal), fp32 — unchanged (passing round-1 kernel)
// ---------------------------------------------------------------------------
__global__ __launch_bounds__(256) void flash_attn(const float* __restrict__ qkv,
                                                  float* __restrict__ out) {
    extern __shared__ float sm[];
    float* Qs = sm;
    float* Ks = Qs + HD * PAD;
    float* Vs = Ks + HD * PAD;
    float* Ps = Vs + 64 * PAD;

    const int tid = threadIdx.x;
    const int tx = tid & 15;
    const int ty = tid >> 4;
    const int qt = blockIdx.x;
    const int h  = blockIdx.y;
    const int b  = blockIdx.z;
    const int q0 = qt * 64;

    const float* qb = qkv + (size_t)b * T_SEQ * C3 + (size_t)h * HD;
    const float* kb = qb + C_DIM;
    const float* vb = qb + 2 * C_DIM;

#pragma unroll
    for (int r = 0; r < 4; r++) {
        int idx = tid + r * 256;
        int i = idx >> 4;
        int d0 = (idx & 15) << 2;
        float4 q4 = *(const float4*)(qb + (size_t)(q0 + i) * C3 + d0);
        Qs[(d0 + 0) * PAD + i] = q4.x;
        Qs[(d0 + 1) * PAD + i] = q4.y;
        Qs[(d0 + 2) * PAD + i] = q4.z;
        Qs[(d0 + 3) * PAD + i] = q4.w;
    }

    float m[4], l[4], o[4][4];
#pragma unroll
    for (int r = 0; r < 4; r++) {
        m[r] = -1e30f;
        l[r] = 0.0f;
#pragma unroll
        for (int c = 0; c < 4; c++) o[r][c] = 0.0f;
    }

    const float scale = 0.125f;

    for (int kt = 0; kt <= qt; kt++) {
        const int k0 = kt * 64;
        __syncthreads();
#pragma unroll
        for (int r = 0; r < 4; r++) {
            int idx = tid + r * 256;
            int j = idx >> 4;
            int d0 = (idx & 15) << 2;
            float4 k4 = *(const float4*)(kb + (size_t)(k0 + j) * C3 + d0);
            Ks[(d0 + 0) * PAD + j] = k4.x;
            Ks[(d0 + 1) * PAD + j] = k4.y;
            Ks[(d0 + 2) * PAD + j] = k4.z;
            Ks[(d0 + 3) * PAD + j] = k4.w;
            float4 v4 = *(const float4*)(vb + (size_t)(k0 + j) * C3 + d0);
            *(float4*)&Vs[j * PAD + d0] = v4;
        }
        __syncthreads();

        float s[4][4];
#pragma unroll
        for (int r = 0; r < 4; r++)
#pragma unroll
            for (int c = 0; c < 4; c++) s[r][c] = 0.0f;

#pragma unroll 8
        for (int d = 0; d < HD; d++) {
            float4 qv = *(const float4*)&Qs[d * PAD + ty * 4];
            float4 kv = *(const float4*)&Ks[d * PAD + tx * 4];
            float qr[4] = {qv.x, qv.y, qv.z, qv.w};
            float kr[4] = {kv.x, kv.y, kv.z, kv.w};
#pragma unroll
            for (int r = 0; r < 4; r++)
#pragma unroll
                for (int c = 0; c < 4; c++) s[r][c] += qr[r] * kr[c];
        }

#pragma unroll
        for (int r = 0; r < 4; r++)
#pragma unroll
            for (int c = 0; c < 4; c++) s[r][c] *= scale;
        if (kt == qt) {
#pragma unroll
            for (int r = 0; r < 4; r++) {
                int ig = ty * 4 + r;
#pragma unroll
                for (int c = 0; c < 4; c++) {
                    int jg = tx * 4 + c;
                    if (jg > ig) s[r][c] = -1e30f;
                }
            }
        }

#pragma unroll
        for (int r = 0; r < 4; r++) {
            float rm = fmaxf(fmaxf(s[r][0], s[r][1]), fmaxf(s[r][2], s[r][3]));
            rm = fmaxf(rm, __shfl_xor_sync(0xffffffffu, rm, 1));
            rm = fmaxf(rm, __shfl_xor_sync(0xffffffffu, rm, 2));
            rm = fmaxf(rm, __shfl_xor_sync(0xffffffffu, rm, 4));
            rm = fmaxf(rm, __shfl_xor_sync(0xffffffffu, rm, 8));
            float mn = fmaxf(m[r], rm);
            float alpha = __expf(m[r] - mn);
            m[r] = mn;
            float rs = 0.0f;
#pragma unroll
            for (int c = 0; c < 4; c++) {
                s[r][c] = __expf(s[r][c] - mn);
                rs += s[r][c];
            }
            rs += __shfl_xor_sync(0xffffffffu, rs, 1);
            rs += __shfl_xor_sync(0xffffffffu, rs, 2);
            rs += __shfl_xor_sync(0xffffffffu, rs, 4);
            rs += __shfl_xor_sync(0xffffffffu, rs, 8);
            l[r] = l[r] * alpha + rs;
#pragma unroll
            for (int c = 0; c < 4; c++) o[r][c] *= alpha;
            *(float4*)&Ps[(ty * 4 + r) * PAD + tx * 4] =
                make_float4(s[r][0], s[r][1], s[r][2], s[r][3]);
        }
        __syncthreads();

#pragma unroll 4
        for (int j = 0; j < 64; j++) {
            float4 v4 = *(const float4*)&Vs[j * PAD + tx * 4];
#pragma unroll
            for (int r = 0; r < 4; r++) {
                float p = Ps[(ty * 4 + r) * PAD + j];
                o[r][0] += p * v4.x;
                o[r][1] += p * v4.y;
                o[r][2] += p * v4.z;
                o[r][3] += p * v4.w;
            }
        }
    }

#pragma unroll
    for (int r = 0; r < 4; r++) {
        float inv = 1.0f / l[r];
        float4 w = make_float4(o[r][0] * inv, o[r][1] * inv,
                               o[r][2] * inv, o[r][3] * inv);
        *(float4*)&out[((size_t)b * T_SEQ + q0 + ty * 4 + r) * C_DIM
                       + h * HD + tx * 4] = w;
    }
}

// ---------------------------------------------------------------------------
extern "C" void kernel_launch(void* const* d_in, const int* in_sizes, int n_in,
                              void* d_out, int out_size) {
    const float* x      = (const float*)d_in[0];
    const float* w_qkv  = (const float*)d_in[1];
    const float* w_proj = (const float*)d_in[2];
    float* out = (float*)d_out;

    float *qkv, *att;
    __nv_bfloat16 *xhi, *xlo, *ahi, *alo, *wqhi, *wqlo, *wphi, *wplo;
    cudaGetSymbolAddress((void**)&qkv, g_qkv);
    cudaGetSymbolAddress((void**)&att, g_att);
    cudaGetSymbolAddress((void**)&xhi, g_xhi);
    cudaGetSymbolAddress((void**)&xlo, g_xlo);
    cudaGetSymbolAddress((void**)&ahi, g_ahi);
    cudaGetSymbolAddress((void**)&alo, g_alo);
    cudaGetSymbolAddress((void**)&wqhi, g_wqhi);
    cudaGetSymbolAddress((void**)&wqlo, g_wqlo);
    cudaGetSymbolAddress((void**)&wphi, g_wphi);
    cudaGetSymbolAddress((void**)&wplo, g_wplo);

    cudaFuncSetAttribute(gemm_mma_bf16x3,
                         cudaFuncAttributeMaxDynamicSharedMemorySize,
                         GSMEM_TOTAL);
    cudaFuncSetAttribute(flash_attn,
                         cudaFuncAttributeMaxDynamicSharedMemorySize,
                         4 * HD * PAD * (int)sizeof(float));

    const int M = MTOT;

    // Splits
    {
        int n4 = M * C_DIM / 4;
        split_bf16<<<(n4 + 255) / 256, 256>>>(x, xhi, xlo, n4);
        n4 = C3 * C_DIM / 4;
        split_bf16<<<(n4 + 255) / 256, 256>>>(w_qkv, wqhi, wqlo, n4);
        n4 = C_DIM * C_DIM / 4;
        split_bf16<<<(n4 + 255) / 256, 256>>>(w_proj, wphi, wplo, n4);
    }

    // 1) qkv = x @ w_qkv^T  (mma.sync bf16x3)
    {
        dim3 grid(C3 / 128, M / 128);
        gemm_mma_bf16x3<<<grid, 256, GSMEM_TOTAL>>>(xhi, xlo, wqhi, wqlo, qkv,
                                                    M, C3, C_DIM);
    }

    // 2) fused causal flash attention (fp32)
    {
        const int smem_bytes = 4 * HD * PAD * (int)sizeof(float);
        dim3 grid(T_SEQ / 64, NH, B_SZ);
        flash_attn<<<grid, 256, smem_bytes>>>(qkv, att);
    }

    // 3) split attention output, then out = att @ w_proj^T
    {
        int n4 = M * C_DIM / 4;
        split_bf16<<<(n4 + 255) / 256, 256>>>(att, ahi, alo, n4);
        dim3 grid(C_DIM / 128, M / 128);
        gemm_mma_bf16x3<<<grid, 256, GSMEM_TOTAL>>>(ahi, alo, wphi, wplo, out,
                                                    M, C_DIM, C_DIM);
    }
}

// round 4
// speedup vs baseline: 2.7797x; 1.6700x over previous
#include <cuda_runtime.h>
#include <cuda_bf16.h>
#include <cstdint>
#include <math.h>

#define B_SZ   4
#define T_SEQ  2048
#define C_DIM  1024
#define C3     3072
#define NH     16
#define HD     64
#define MTOT   (B_SZ * T_SEQ)   // 8192

// ---------------------------------------------------------------------------
// Scratch (__device__ globals; no allocation allowed)
// ---------------------------------------------------------------------------
__device__ __nv_bfloat16 g_qkvhi[(size_t)MTOT * C3];
__device__ __nv_bfloat16 g_qkvlo[(size_t)MTOT * C3];
__device__ __nv_bfloat16 g_xhi[(size_t)MTOT * C_DIM];
__device__ __nv_bfloat16 g_xlo[(size_t)MTOT * C_DIM];
__device__ __nv_bfloat16 g_ahi[(size_t)MTOT * C_DIM];
__device__ __nv_bfloat16 g_alo[(size_t)MTOT * C_DIM];
__device__ __nv_bfloat16 g_wqhi[(size_t)C3 * C_DIM];
__device__ __nv_bfloat16 g_wqlo[(size_t)C3 * C_DIM];
__device__ __nv_bfloat16 g_wphi[(size_t)C_DIM * C_DIM];
__device__ __nv_bfloat16 g_wplo[(size_t)C_DIM * C_DIM];

// ---------------------------------------------------------------------------
// Baseline-PTX building blocks (sm_80+, compile under plain compute_103)
// ---------------------------------------------------------------------------
__device__ __forceinline__ uint32_t smem_u32(const void* p) {
    uint32_t a;
    asm("{ .reg .u64 t; cvta.to.shared.u64 t, %1; cvt.u32.u64 %0, t; }"
        : "=r"(a) : "l"(p));
    return a;
}

#define CP_ASYNC16(saddr, gptr) \
    asm volatile("cp.async.cg.shared.global [%0], [%1], 16;" \
                 :: "r"(saddr), "l"(gptr))
#define CP_COMMIT() asm volatile("cp.async.commit_group;" ::: "memory")
#define CP_WAIT(n)  asm volatile("cp.async.wait_group %0;" :: "n"(n) : "memory")

#define LDMATRIX_X4(R, addr) \
    asm volatile("ldmatrix.sync.aligned.m8n8.x4.shared.b16 {%0,%1,%2,%3}, [%4];" \
                 : "=r"((R)[0]), "=r"((R)[1]), "=r"((R)[2]), "=r"((R)[3]) \
                 : "r"(addr))

#define LDMATRIX_X4_T(R, addr) \
    asm volatile("ldmatrix.sync.aligned.m8n8.x4.trans.shared.b16 {%0,%1,%2,%3}, [%4];" \
                 : "=r"((R)[0]), "=r"((R)[1]), "=r"((R)[2]), "=r"((R)[3]) \
                 : "r"(addr))

#define MMA16816(D, A, B0, B1) \
    asm volatile("mma.sync.aligned.m16n8k16.row.col.f32.bf16.bf16.f32 " \
                 "{%0,%1,%2,%3}, {%4,%5,%6,%7}, {%8,%9}, {%0,%1,%2,%3};" \
                 : "+f"((D)[0]), "+f"((D)[1]), "+f"((D)[2]), "+f"((D)[3]) \
                 : "r"((A)[0]), "r"((A)[1]), "r"((A)[2]), "r"((A)[3]), \
                   "r"(B0), "r"(B1))

// Split two fp32 into packed bf16x2 hi + lo streams (a -> low half).
__device__ __forceinline__ void split_pack2(float a, float b,
                                            uint32_t& hi, uint32_t& lo) {
    uint32_t h;
    asm("cvt.rn.bf16x2.f32 %0, %1, %2;" : "=r"(h) : "f"(b), "f"(a));
    float ah = __uint_as_float(h << 16);
    float bh = __uint_as_float(h & 0xFFFF0000u);
    float al = a - ah;
    float bl = b - bh;
    uint32_t l;
    asm("cvt.rn.bf16x2.f32 %0, %1, %2;" : "=r"(l) : "f"(bl), "f"(al));
    hi = h; lo = l;
}

// ---------------------------------------------------------------------------
// fp32 -> (bf16 hi, bf16 lo) split (inputs only: x, weights)
// ---------------------------------------------------------------------------
__global__ void split_bf16(const float* __restrict__ x,
                           __nv_bfloat16* __restrict__ hi,
                           __nv_bfloat16* __restrict__ lo, int n4) {
    int i = blockIdx.x * blockDim.x + threadIdx.x;
    if (i >= n4) return;
    float4 v = ((const float4*)x)[i];
    uint32_t h0, l0, h1, l1;
    split_pack2(v.x, v.y, h0, l0);
    split_pack2(v.z, v.w, h1, l1);
    ((uint32_t*)hi)[2 * i]     = h0;
    ((uint32_t*)hi)[2 * i + 1] = h1;
    ((uint32_t*)lo)[2 * i]     = l0;
    ((uint32_t*)lo)[2 * i + 1] = l1;
}

// ---------------------------------------------------------------------------
// bf16x3 GEMM NT via mma.sync: C[m,n] = sum_k A[m,k]*B[n,k], fp32-accurate.
// Epilogue: either fp32 (Cf) or bf16 hi/lo split (Chi/Clo). Columns
// < scale_limit are multiplied by 0.125 (exact in the split).
// ---------------------------------------------------------------------------
#define BK 32
#define SSTRIDE 40
#define SROWB (SSTRIDE * 2)
#define TILE_SMB (128 * SROWB)
#define STAGE_SMB (4 * TILE_SMB)
#define GSMEM_TOTAL (2 * STAGE_SMB)   // 81920

__global__ __launch_bounds__(256)
void gemm_mma_bf16x3(const __nv_bfloat16* __restrict__ Ahi,
                     const __nv_bfloat16* __restrict__ Alo,
                     const __nv_bfloat16* __restrict__ Bhi,
                     const __nv_bfloat16* __restrict__ Blo,
                     float* __restrict__ Cf,
                     __nv_bfloat16* __restrict__ Chi,
                     __nv_bfloat16* __restrict__ Clo,
                     int scale_limit, int M, int N, int K) {
    extern __shared__ char smem[];
    const uint32_t sb = smem_u32(smem);
    const int tid  = threadIdx.x;
    const int wid  = tid >> 5;
    const int lane = tid & 31;
    const int bm = blockIdx.y * 128;
    const int bn = blockIdx.x * 128;
    const int wm = (wid >> 2) * 64;
    const int wn = (wid & 3) * 32;

    float acc[4][4][4];
#pragma unroll
    for (int mt = 0; mt < 4; mt++)
#pragma unroll
        for (int nt = 0; nt < 4; nt++)
#pragma unroll
            for (int r = 0; r < 4; r++) acc[mt][nt][r] = 0.0f;

    auto load_stage = [&](int chunk, int buf) {
        const uint32_t stage = sb + buf * STAGE_SMB;
        const size_t k0 = (size_t)chunk * BK;
#pragma unroll
        for (int i = 0; i < 2; i++) {
            const int id  = tid + i * 256;
            const int row = id >> 2;
            const int c8  = id & 3;
            const uint32_t soff = (uint32_t)(row * SROWB + c8 * 16);
            const size_t aoff = (size_t)(bm + row) * K + k0 + c8 * 8;
            const size_t boff = (size_t)(bn + row) * K + k0 + c8 * 8;
            CP_ASYNC16(stage + soff,                Ahi + aoff);
            CP_ASYNC16(stage + TILE_SMB + soff,     Alo + aoff);
            CP_ASYNC16(stage + 2 * TILE_SMB + soff, Bhi + boff);
            CP_ASYNC16(stage + 3 * TILE_SMB + soff, Blo + boff);
        }
    };

    const int nch = K / BK;
    load_stage(0, 0);
    CP_COMMIT();

    const uint32_t a_row = (uint32_t)(lane & 15);
    const uint32_t a_col = (uint32_t)((lane >> 4) << 3);
    const uint32_t b_row = (uint32_t)(((lane >> 4) << 3) + (lane & 7));
    const uint32_t b_col = (uint32_t)(((lane >> 3) & 1) << 3);

    for (int c = 0; c < nch; c++) {
        const int buf = c & 1;
        if (c + 1 < nch) {
            load_stage(c + 1, buf ^ 1);
            CP_COMMIT();
            CP_WAIT(1);
        } else {
            CP_WAIT(0);
        }
        __syncthreads();

        const uint32_t sAh = sb + buf * STAGE_SMB;
        const uint32_t sAl = sAh + TILE_SMB;
        const uint32_t sBh = sAh + 2 * TILE_SMB;
        const uint32_t sBl = sAh + 3 * TILE_SMB;

#pragma unroll
        for (int ks = 0; ks < 2; ks++) {
            const uint32_t k0 = ks * 16;
            uint32_t ah[4][4], al[4][4], bh[2][4], bl[2][4];
#pragma unroll
            for (int mt = 0; mt < 4; mt++) {
                const uint32_t off = (uint32_t)(wm + mt * 16 + a_row) * SROWB
                                   + (k0 + a_col) * 2;
                LDMATRIX_X4(ah[mt], sAh + off);
                LDMATRIX_X4(al[mt], sAl + off);
            }
#pragma unroll
            for (int ng = 0; ng < 2; ng++) {
                const uint32_t off = (uint32_t)(wn + ng * 16 + b_row) * SROWB
                                   + (k0 + b_col) * 2;
                LDMATRIX_X4(bh[ng], sBh + off);
                LDMATRIX_X4(bl[ng], sBl + off);
            }
#pragma unroll
            for (int mt = 0; mt < 4; mt++) {
#pragma unroll
                for (int nt = 0; nt < 4; nt++) {
                    const int ng = nt >> 1;
                    const int rb = (nt & 1) * 2;
                    MMA16816(acc[mt][nt], ah[mt], bh[ng][rb], bh[ng][rb + 1]);
                    MMA16816(acc[mt][nt], ah[mt], bl[ng][rb], bl[ng][rb + 1]);
                    MMA16816(acc[mt][nt], al[mt], bh[ng][rb], bh[ng][rb + 1]);
                }
            }
        }
        __syncthreads();
    }

    const int erow = bm + wm + (lane >> 2);
    const int ecol = bn + wn + (lane & 3) * 2;
#pragma unroll
    for (int mt = 0; mt < 4; mt++) {
#pragma unroll
        for (int nt = 0; nt < 4; nt++) {
            float v0 = acc[mt][nt][0], v1 = acc[mt][nt][1];
            float v2 = acc[mt][nt][2], v3 = acc[mt][nt][3];
            const int colg = ecol + nt * 8;
            if (colg < scale_limit) {
                v0 *= 0.125f; v1 *= 0.125f; v2 *= 0.125f; v3 *= 0.125f;
            }
            const size_t p0 = (size_t)(erow + mt * 16) * N + colg;
            const size_t p1 = p0 + 8 * (size_t)N;
            if (Cf) {
                *(float2*)(Cf + p0) = make_float2(v0, v1);
                *(float2*)(Cf + p1) = make_float2(v2, v3);
            } else {
                uint32_t h, l;
                split_pack2(v0, v1, h, l);
                *(uint32_t*)(Chi + p0) = h;
                *(uint32_t*)(Clo + p0) = l;
                split_pack2(v2, v3, h, l);
                *(uint32_t*)(Chi + p1) = h;
                *(uint32_t*)(Clo + p1) = l;
            }
        }
    }
}

// ---------------------------------------------------------------------------
// Tensor-core causal flash attention (bf16x3, fp32 softmax/accum).
// CTA: 128 q rows, 8 warps x 16 rows. 64-key chunks, double-buffered cp.async.
// Q is pre-scaled by 1/8 (done in GEMM1 epilogue). Output written as split.
// ---------------------------------------------------------------------------
#define FROWB 144                  // 72 bf16 per smem row (64 + 8 pad)
#define FTILE (64 * FROWB)         // 9216
#define FSTAGE (4 * FTILE)         // 36864: Khi,Klo,Vhi,Vlo
#define FSMEM (2 * FSTAGE)         // 73728

__global__ __launch_bounds__(256)
void flash_mma(const __nv_bfloat16* __restrict__ qkvh,
               const __nv_bfloat16* __restrict__ qkvl,
               __nv_bfloat16* __restrict__ ohi,
               __nv_bfloat16* __restrict__ olo) {
    extern __shared__ char smem[];
    const uint32_t sb = smem_u32(smem);
    const int tid  = threadIdx.x;
    const int wid  = tid >> 5;
    const int lane = tid & 31;
    const int qt = blockIdx.x;
    const int h  = blockIdx.y;
    const int b  = blockIdx.z;
    const int q0 = qt * 128;
    const size_t m0 = (size_t)b * T_SEQ;
    const int qcol = h * HD;
    const int kcol = C_DIM + h * HD;
    const int vcol = 2 * C_DIM + h * HD;
    const int wm = wid * 16;

    // ---- Stage Q tile (hi @ sb, lo @ sb+18432), plain vector loads
#pragma unroll
    for (int i = 0; i < 8; i++) {
        const int e = tid + i * 256;        // 0..2047
        const int part = e >> 10;
        const int rr = (e >> 3) & 127;
        const int c8 = e & 7;
        const __nv_bfloat16* src = (part ? qkvl : qkvh)
            + (m0 + q0 + rr) * C3 + qcol + c8 * 8;
        *(uint4*)(smem + part * 18432 + rr * FROWB + c8 * 16) =
            *(const uint4*)src;
    }
    __syncthreads();

    uint32_t qh[4][4], ql[4][4];
    {
        const uint32_t arow = lane & 15;
        const uint32_t acol = (uint32_t)((lane >> 4) << 3);
#pragma unroll
        for (int ks = 0; ks < 4; ks++) {
            const uint32_t off = (uint32_t)(wm + arow) * FROWB
                               + (ks * 16 + acol) * 2;
            LDMATRIX_X4(qh[ks], sb + off);
            LDMATRIX_X4(ql[ks], sb + 18432 + off);
        }
    }
    __syncthreads();

    float mr0 = -1e30f, mr1 = -1e30f, lr0 = 0.0f, lr1 = 0.0f;
    float oacc[8][4];
#pragma unroll
    for (int t = 0; t < 8; t++)
#pragma unroll
        for (int r = 0; r < 4; r++) oacc[t][r] = 0.0f;

    const int nch = 2 * (qt + 1);

    auto stage = [&](int c, int buf) {
        const int tile = tid >> 6;          // 0:Khi 1:Klo 2:Vhi 3:Vlo
        const int row  = tid & 63;
        const __nv_bfloat16* base = (tile & 1) ? qkvl : qkvh;
        const int col = (tile < 2) ? kcol : vcol;
        const __nv_bfloat16* src =
            base + (m0 + (size_t)c * 64 + row) * C3 + col;
        const uint32_t dst = sb + buf * FSTAGE + tile * FTILE + row * FROWB;
#pragma unroll
        for (int c8 = 0; c8 < 8; c8++)
            CP_ASYNC16(dst + c8 * 16, src + c8 * 8);
    };

    stage(0, 0);
    CP_COMMIT();

    const uint32_t brow = (uint32_t)(((lane >> 4) << 3) + (lane & 7));
    const uint32_t bcol = (uint32_t)(((lane >> 3) & 1) << 3);
    const uint32_t trow = (uint32_t)(lane & 15);
    const uint32_t tcol = (uint32_t)((lane >> 4) << 3);
    const int rloc = lane >> 2;

    for (int c = 0; c < nch; c++) {
        const int buf = c & 1;
        if (c + 1 < nch) { stage(c + 1, buf ^ 1); CP_COMMIT(); CP_WAIT(1); }
        else             { CP_WAIT(0); }
        __syncthreads();

        const int k0 = c * 64;
        if (k0 <= q0 + wm + 15) {          // warp has unmasked work here
            const uint32_t sKh = sb + buf * FSTAGE;
            const uint32_t sKl = sKh + FTILE;
            const uint32_t sVh = sKh + 2 * FTILE;
            const uint32_t sVl = sKh + 3 * FTILE;

            float sc[8][4];
#pragma unroll
            for (int t = 0; t < 8; t++)
#pragma unroll
                for (int r = 0; r < 4; r++) sc[t][r] = 0.0f;

#pragma unroll
            for (int ks = 0; ks < 4; ks++) {
#pragma unroll
                for (int ng = 0; ng < 4; ng++) {
                    uint32_t kh[4], kl[4];
                    const uint32_t off = (uint32_t)(ng * 16 + brow) * FROWB
                                       + (ks * 16 + bcol) * 2;
                    LDMATRIX_X4(kh, sKh + off);
                    LDMATRIX_X4(kl, sKl + off);
                    MMA16816(sc[2 * ng],     qh[ks], kh[0], kh[1]);
                    MMA16816(sc[2 * ng],     qh[ks], kl[0], kl[1]);
                    MMA16816(sc[2 * ng],     ql[ks], kh[0], kh[1]);
                    MMA16816(sc[2 * ng + 1], qh[ks], kh[2], kh[3]);
                    MMA16816(sc[2 * ng + 1], qh[ks], kl[2], kl[3]);
                    MMA16816(sc[2 * ng + 1], ql[ks], kh[2], kh[3]);
                }
            }

            // causal mask (diag-overlapping chunks only)
            const int row0 = q0 + wm + rloc;
            if (k0 + 63 > row0) {
#pragma unroll
                for (int t = 0; t < 8; t++) {
                    const int colb = k0 + t * 8 + (lane & 3) * 2;
                    if (colb     > row0)     sc[t][0] = -1e30f;
                    if (colb + 1 > row0)     sc[t][1] = -1e30f;
                    if (colb     > row0 + 8) sc[t][2] = -1e30f;
                    if (colb + 1 > row0 + 8) sc[t][3] = -1e30f;
                }
            }

            // online softmax
            float mx0 = -1e30f, mx1 = -1e30f;
#pragma unroll
            for (int t = 0; t < 8; t++) {
                mx0 = fmaxf(mx0, fmaxf(sc[t][0], sc[t][1]));
                mx1 = fmaxf(mx1, fmaxf(sc[t][2], sc[t][3]));
            }
            mx0 = fmaxf(mx0, __shfl_xor_sync(0xffffffffu, mx0, 1));
            mx0 = fmaxf(mx0, __shfl_xor_sync(0xffffffffu, mx0, 2));
            mx1 = fmaxf(mx1, __shfl_xor_sync(0xffffffffu, mx1, 1));
            mx1 = fmaxf(mx1, __shfl_xor_sync(0xffffffffu, mx1, 2));
            const float mn0 = fmaxf(mr0, mx0);
            const float mn1 = fmaxf(mr1, mx1);
            const float a0 = __expf(mr0 - mn0);
            const float a1 = __expf(mr1 - mn1);
            mr0 = mn0; mr1 = mn1;
            float s0 = 0.0f, s1 = 0.0f;
#pragma unroll
            for (int t = 0; t < 8; t++) {
                sc[t][0] = __expf(sc[t][0] - mn0); s0 += sc[t][0];
                sc[t][1] = __expf(sc[t][1] - mn0); s0 += sc[t][1];
                sc[t][2] = __expf(sc[t][2] - mn1); s1 += sc[t][2];
                sc[t][3] = __expf(sc[t][3] - mn1); s1 += sc[t][3];
            }
            s0 += __shfl_xor_sync(0xffffffffu, s0, 1);
            s0 += __shfl_xor_sync(0xffffffffu, s0, 2);
            s1 += __shfl_xor_sync(0xffffffffu, s1, 1);
            s1 += __shfl_xor_sync(0xffffffffu, s1, 2);
            lr0 = lr0 * a0 + s0;
            lr1 = lr1 * a1 + s1;
#pragma unroll
            for (int t = 0; t < 8; t++) {
                oacc[t][0] *= a0; oacc[t][1] *= a0;
                oacc[t][2] *= a1; oacc[t][3] *= a1;
            }

            // O += P * V (P from registers, split hi/lo)
#pragma unroll
            for (int ks = 0; ks < 4; ks++) {
                uint32_t ph[4], pl[4];
                split_pack2(sc[2 * ks][0],     sc[2 * ks][1],     ph[0], pl[0]);
                split_pack2(sc[2 * ks][2],     sc[2 * ks][3],     ph[1], pl[1]);
                split_pack2(sc[2 * ks + 1][0], sc[2 * ks + 1][1], ph[2], pl[2]);
                split_pack2(sc[2 * ks + 1][2], sc[2 * ks + 1][3], ph[3], pl[3]);
#pragma unroll
                for (int ng = 0; ng < 4; ng++) {
                    uint32_t vh[4], vl[4];
                    const uint32_t off = (uint32_t)(ks * 16 + trow) * FROWB
                                       + (ng * 16 + tcol) * 2;
                    LDMATRIX_X4_T(vh, sVh + off);
                    LDMATRIX_X4_T(vl, sVl + off);
                    MMA16816(oacc[2 * ng],     ph, vh[0], vh[1]);
                    MMA16816(oacc[2 * ng],     ph, vl[0], vl[1]);
                    MMA16816(oacc[2 * ng],     pl, vh[0], vh[1]);
                    MMA16816(oacc[2 * ng + 1], ph, vh[2], vh[3]);
                    MMA16816(oacc[2 * ng + 1], ph, vl[2], vl[3]);
                    MMA16816(oacc[2 * ng + 1], pl, vh[2], vh[3]);
                }
            }
        }
        __syncthreads();
    }

    // Epilogue: normalize, split to bf16 hi/lo, store [B,T,C]
    const float i0 = 1.0f / lr0;
    const float i1 = 1.0f / lr1;
    const size_t g0 = (m0 + q0 + wm + rloc) * C_DIM + h * HD;
    const size_t g1 = g0 + 8 * (size_t)C_DIM;
#pragma unroll
    for (int t = 0; t < 8; t++) {
        const int col = t * 8 + (lane & 3) * 2;
        uint32_t hh, ll;
        split_pack2(oacc[t][0] * i0, oacc[t][1] * i0, hh, ll);
        *(uint32_t*)(ohi + g0 + col) = hh;
        *(uint32_t*)(olo + g0 + col) = ll;
        split_pack2(oacc[t][2] * i1, oacc[t][3] * i1, hh, ll);
        *(uint32_t*)(ohi + g1 + col) = hh;
        *(uint32_t*)(olo + g1 + col) = ll;
    }
}

// ---------------------------------------------------------------------------
extern "C" void kernel_launch(void* const* d_in, const int* in_sizes, int n_in,
                              void* d_out, int out_size) {
    const float* x      = (const float*)d_in[0];
    const float* w_qkv  = (const float*)d_in[1];
    const float* w_proj = (const float*)d_in[2];
    float* out = (float*)d_out;

    __nv_bfloat16 *qkvh, *qkvl, *xhi, *xlo, *ahi, *alo;
    __nv_bfloat16 *wqhi, *wqlo, *wphi, *wplo;
    cudaGetSymbolAddress((void**)&qkvh, g_qkvhi);
    cudaGetSymbolAddress((void**)&qkvl, g_qkvlo);
    cudaGetSymbolAddress((void**)&xhi, g_xhi);
    cudaGetSymbolAddress((void**)&xlo, g_xlo);
    cudaGetSymbolAddress((void**)&ahi, g_ahi);
    cudaGetSymbolAddress((void**)&alo, g_alo);
    cudaGetSymbolAddress((void**)&wqhi, g_wqhi);
    cudaGetSymbolAddress((void**)&wqlo, g_wqlo);
    cudaGetSymbolAddress((void**)&wphi, g_wphi);
    cudaGetSymbolAddress((void**)&wplo, g_wplo);

    cudaFuncSetAttribute(gemm_mma_bf16x3,
                         cudaFuncAttributeMaxDynamicSharedMemorySize,
                         GSMEM_TOTAL);
    cudaFuncSetAttribute(flash_mma,
                         cudaFuncAttributeMaxDynamicSharedMemorySize,
                         FSMEM);

    const int M = MTOT;

    // Input splits
    {
        int n4 = M * C_DIM / 4;
        split_bf16<<<(n4 + 255) / 256, 256>>>(x, xhi, xlo, n4);
        n4 = C3 * C_DIM / 4;
        split_bf16<<<(n4 + 255) / 256, 256>>>(w_qkv, wqhi, wqlo, n4);
        n4 = C_DIM * C_DIM / 4;
        split_bf16<<<(n4 + 255) / 256, 256>>>(w_proj, wphi, wplo, n4);
    }

    // 1) qkv = x @ w_qkv^T -> split bf16, q-block pre-scaled by 1/8
    {
        dim3 grid(C3 / 128, M / 128);
        gemm_mma_bf16x3<<<grid, 256, GSMEM_TOTAL>>>(
            xhi, xlo, wqhi, wqlo, nullptr, qkvh, qkvl, C_DIM, M, C3, C_DIM);
    }

    // 2) causal flash attention (tensor cores) -> split bf16
    {
        dim3 grid(T_SEQ / 128, NH, B_SZ);
        flash_mma<<<grid, 256, FSMEM>>>(qkvh, qkvl, ahi, alo);
    }

    // 3) out = att @ w_proj^T -> fp32
    {
        dim3 grid(C_DIM / 128, M / 128);
        gemm_mma_bf16x3<<<grid, 256, GSMEM_TOTAL>>>(
            ahi, alo, wphi, wplo, out, nullptr, nullptr, 0, M, C_DIM, C_DIM);
    }
}